// round 16
// baseline (speedup 1.0000x reference)
#include <cuda_runtime.h>
#include <cuda_bf16.h>

#define FULLMASK 0xffffffffu

__device__ float g_den4[1024];   // [b][chunk]
__device__ float g_num4[1024];   // [b][chunk]

// Group-scoped barrier: group g (64 threads = 2 warps) syncs on bar g+1.
__device__ __forceinline__ void gbar(int g) {
    asm volatile("bar.sync %0, %1;" :: "r"(g + 1), "r"(64) : "memory");
}

// One CTA = 256 threads = ONE batch x FOUR time-chunks (grid B=256, occ 1):
//   group 0: exact alpha_0, steps 1..E0, emits log||alpha_E0||.
//   group j>0: uniform start at E[j-1]-11, 12 burn-in steps (Birkhoff
//     contraction ~0.1/step), snapshot at E[j-1], run to E[j]; emits growth
//     log||alpha_Ej|| - log||alpha_E[j-1]||  (scale cancels; last chunk
//     folds e^end into its final norm). Sequential depth ~S/4 + 12.
// Thread owns TWO adjacent columns; 128 HFMA2/step; e[0] free rescale.
__global__ void __launch_bounds__(256, 1) k_crf_forward(
    const float* __restrict__ feats,   // [B,S,L]
    const float* __restrict__ startT,  // [L]
    const float* __restrict__ endT,    // [L]
    const float* __restrict__ trans,   // [L,L]
    const int*   __restrict__ mask,    // [B,S]
    const int*   __restrict__ labels,  // [B,S]
    int S, int E0, int E1, int E2)
{
    constexpr int L = 128;
    extern __shared__ char sm[];
    char*  ebuf  = sm;                                 // [4 groups][2 phases][256B]
    int*   smask = (int*)(sm + 2048);                  // [S]
    float* sred  = (float*)(sm + 2048 + S * 4);        // [4 groups][4]

    const int tid = threadIdx.x;
    const int g   = tid >> 6;          // chunk 0..3
    const int lt  = tid & 63;
    const int wg  = (tid >> 5) & 1;
    const int b   = blockIdx.x;
    const int c0  = 2 * lt;
    const int c1  = 2 * lt + 1;

    const int eprev = (g == 0) ? 0 : (g == 1 ? E0 : (g == 2 ? E1 : E2));
    const int eend  = (g == 0) ? E0 : (g == 1 ? E1 : (g == 2 ? E2 : S - 1));
    int sb = (g == 0) ? 1 : eprev - 11;      // 12 burn-in steps for g>0
    if (sb < 1) sb = 1;

    const float*  fb  = feats + (size_t)b * S * L;
    const float2* fb2 = (const float2*)fb;             // [S][64]
    char* gbuf = ebuf + g * 512;

    // ---- expT slices (all groups need the same matrix) ----
    __nv_bfloat162 T0[64], T1[64];
    #pragma unroll
    for (int k = 0; k < 64; ++k) {
        const float* r0 = trans + (size_t)(2 * k) * L;
        const float* r1 = trans + (size_t)(2 * k + 1) * L;
        T0[k] = __floats2bfloat162_rn(__expf(__ldg(r0 + c0)), __expf(__ldg(r1 + c0)));
        T1[k] = __floats2bfloat162_rn(__expf(__ldg(r0 + c1)), __expf(__ldg(r1 + c1)));
    }
    for (int k = tid; k < S; k += 256) smask[k] = mask[b * S + k];
    __syncthreads();                   // smask visible to all groups

    // ---- chunk-local init ----
    float v0, v1, offset;
    if (g == 0) {
        float a00 = startT[c0] + fb[c0];
        float a01 = startT[c1] + fb[c1];
        float mv = fmaxf(a00, a01);
        #pragma unroll
        for (int o = 16; o; o >>= 1) mv = fmaxf(mv, __shfl_xor_sync(FULLMASK, mv, o));
        if ((lt & 31) == 0) sred[4 * g + wg] = mv;
        gbar(g);
        float m0 = fmaxf(sred[4 * g], sred[4 * g + 1]);
        gbar(g);
        v0 = __expf(a00 - m0);
        v1 = __expf(a01 - m0);
        offset = m0;
    } else {
        v0 = 1.0f; v1 = 1.0f; offset = 0.0f;   // uniform; burn-in fixes direction
    }
    {
        unsigned hb0 = (__float_as_uint(v0) + 0x8000u) >> 16;
        unsigned hb1 = (__float_as_uint(v1) + 0x8000u) >> 16;
        *(unsigned*)(gbuf + (sb & 1) * 256 + 4 * lt) = hb0 | (hb1 << 16);
    }

    // exp(feat) pipeline
    float2 f1 = fb2[(size_t)sb * 64 + lt];
    float e1x = __expf(f1.x), e1y = __expf(f1.y);
    float2 raw1 = (sb + 1 < S) ? fb2[(size_t)(sb + 1) * 64 + lt] : make_float2(0.f, 0.f);
    float2 raw2 = (sb + 2 < S) ? fb2[(size_t)(sb + 2) * 64 + lt] : make_float2(0.f, 0.f);
    gbar(g);

    const __nv_bfloat162 bz = __floats2bfloat162_rn(0.f, 0.f);

    #define CRF_STEP(T_)                                                          \
    {                                                                             \
        const uint4* se = (const uint4*)(gbuf + ((T_) & 1) * 256);                \
        char*        wbp = gbuf + (((T_) & 1) ^ 1) * 256;                         \
        __nv_bfloat162 x0 = bz, x1 = bz, x2 = bz, x3 = bz;                        \
        __nv_bfloat162 y0 = bz, y1 = bz, y2 = bz, y3 = bz;                        \
        unsigned e0bits = 0;                                                      \
        _Pragma("unroll")                                                         \
        for (int p = 0; p < 16; ++p) {                                            \
            uint4 q = se[p];                                                      \
            __nv_bfloat162 q0 = *(__nv_bfloat162*)&q.x;                           \
            __nv_bfloat162 q1 = *(__nv_bfloat162*)&q.y;                           \
            __nv_bfloat162 q2 = *(__nv_bfloat162*)&q.z;                           \
            __nv_bfloat162 q3 = *(__nv_bfloat162*)&q.w;                           \
            if (p == 0) e0bits = q.x;                                             \
            x0 = __hfma2(q0, T0[4 * p + 0], x0);                                  \
            y0 = __hfma2(q0, T1[4 * p + 0], y0);                                  \
            x1 = __hfma2(q1, T0[4 * p + 1], x1);                                  \
            y1 = __hfma2(q1, T1[4 * p + 1], y1);                                  \
            x2 = __hfma2(q2, T0[4 * p + 2], x2);                                  \
            y2 = __hfma2(q2, T1[4 * p + 2], y2);                                  \
            x3 = __hfma2(q3, T0[4 * p + 3], x3);                                  \
            y3 = __hfma2(q3, T1[4 * p + 3], y3);                                  \
        }                                                                         \
        x0 = __hadd2(x0, x1); x2 = __hadd2(x2, x3); x0 = __hadd2(x0, x2);         \
        y0 = __hadd2(y0, y1); y2 = __hadd2(y2, y3); y0 = __hadd2(y0, y2);         \
        unsigned pa = *(unsigned*)&x0;                                            \
        unsigned pb = *(unsigned*)&y0;                                            \
        float s0 = __uint_as_float(pa << 16) + __uint_as_float(pa & 0xffff0000u); \
        float s1 = __uint_as_float(pb << 16) + __uint_as_float(pb & 0xffff0000u); \
        float eC0 = e1x, eC1 = e1y;                                               \
        e1x = __expf(raw1.x); e1y = __expf(raw1.y);                               \
        raw1 = raw2;                                                              \
        if ((T_) + 3 < S) raw2 = fb2[(size_t)((T_) + 3) * 64 + lt];               \
        float m0f = eC0, m1f = eC1;                                               \
        int mk = smask[T_];                                                       \
        if (((T_) & 3) == 0) {                                                    \
            float e0f = __uint_as_float(e0bits << 16);                            \
            float r = __frcp_rn(e0f);                                             \
            m0f *= r; m1f *= r;                                                   \
            if (mk) offset += __logf(e0f);                                        \
        }                                                                         \
        float nv0 = s0 * m0f, nv1 = s1 * m1f;                                     \
        v0 = mk ? nv0 : v0;                                                       \
        v1 = mk ? nv1 : v1;                                                       \
        unsigned hb0 = (__float_as_uint(v0) + 0x8000u) >> 16;                     \
        unsigned hb1 = (__float_as_uint(v1) + 0x8000u) >> 16;                     \
        *(unsigned*)(wbp + 4 * lt) = hb0 | (hb1 << 16);                           \
        gbar(g);                                                                  \
    }

    // group-sum helper (2 warps)
    #define GSUM(val, dst)                                                        \
    {                                                                             \
        float _s = (val);                                                         \
        _Pragma("unroll")                                                         \
        for (int o = 16; o; o >>= 1) _s += __shfl_xor_sync(FULLMASK, _s, o);      \
        if ((lt & 31) == 0) sred[4 * g + wg] = _s;                                \
        gbar(g);                                                                  \
        (dst) = sred[4 * g] + sred[4 * g + 1];                                    \
        gbar(g);                                                                  \
    }

    // ---- burn-in + snapshot at eprev (g>0 only; for g=0 loop is empty) ----
    float snapStart = 0.f;
    for (int t = sb; t <= eprev; ++t) CRF_STEP(t)
    if (g > 0) {
        float sv; GSUM(v0 + v1, sv)
        snapStart = offset + __logf(sv);
    }

    // ---- main range: (eprev or 0)+1 .. eend ----
    for (int t = eprev + 1; t <= eend; ++t) CRF_STEP(t)

    float snapEnd;
    if (g == 3) {
        float ce; GSUM(v0 * __expf(endT[c0]) + v1 * __expf(endT[c1]), ce)
        snapEnd = offset + __logf(ce);
    } else {
        float sv; GSUM(v0 + v1, sv)
        snapEnd = offset + __logf(sv);
    }
    if (lt == 0) g_den4[4 * b + g] = (g == 0) ? snapEnd : (snapEnd - snapStart);
    #undef CRF_STEP

    // ---- numerator: split by t-range ----
    float num = 0.f;
    const int* lb = labels + b * S;
    if (g == 0) {
        for (int k = lt; k <= eend; k += 64) {
            int mk = smask[k];
            int lab = lb[k]; if (lab == -100) lab = 0;
            if (k == 0) {
                num += startT[lab] + fb[lab];
            } else if (mk) {
                int lp = lb[k - 1]; if (lp == -100) lp = 0;
                num += trans[lp * L + lab] + fb[(size_t)k * L + lab];
            }
        }
        float nt; GSUM(num, nt)
        if (lt == 0) g_num4[4 * b] = nt;
    } else {
        for (int k = eprev + 1 + lt; k <= eend; k += 64) {
            if (smask[k]) {
                int lab = lb[k]; if (lab == -100) lab = 0;
                int lp  = lb[k - 1]; if (lp == -100) lp = 0;
                num += trans[lp * L + lab] + fb[(size_t)k * L + lab];
            }
        }
        float nt; GSUM(num, nt)
        if (g == 3) {
            float slf = 0.f;
            for (int k = lt; k < S; k += 64) slf += (float)smask[k];
            float st; GSUM(slf, st)
            if (lt == 0) {
                int lastt = (int)(st + 0.5f) - 1;
                if (lastt < 0) lastt = 0;
                int lastlab = lb[lastt]; if (lastlab == -100) lastlab = 0;
                g_num4[4 * b + 3] = nt + endT[lastlab];
            }
        } else {
            if (lt == 0) g_num4[4 * b + g] = nt;
        }
    }
    #undef GSUM
}

__global__ void k_finalize(float* __restrict__ out, const float* __restrict__ conf,
                           int B) {
    int t = threadIdx.x;
    float x = 0.f;
    if (t < B) {
        float den = (g_den4[4 * t] + g_den4[4 * t + 1])
                  + (g_den4[4 * t + 2] + g_den4[4 * t + 3]);
        float num = (g_num4[4 * t] + g_num4[4 * t + 1])
                  + (g_num4[4 * t + 2] + g_num4[4 * t + 3]);
        x = (den - num) * conf[t];
    }
    #pragma unroll
    for (int o = 16; o; o >>= 1) x += __shfl_xor_sync(FULLMASK, x, o);
    __shared__ float sh[8];
    if ((t & 31) == 0) sh[t >> 5] = x;
    __syncthreads();
    if (t == 0) {
        float s = 0.f;
        int nw = (blockDim.x + 31) >> 5;
        for (int w = 0; w < nw; ++w) s += sh[w];
        out[0] = s / (float)B;
    }
}

extern "C" void kernel_launch(void* const* d_in, const int* in_sizes, int n_in,
                              void* d_out, int out_size) {
    const float* feats  = (const float*)d_in[0];
    const float* startT = (const float*)d_in[1];
    const float* endT   = (const float*)d_in[2];
    const float* trans  = (const float*)d_in[3];
    const float* conf   = (const float*)d_in[4];
    const int*   mask   = (const int*)  d_in[5];
    const int*   labels = (const int*)  d_in[6];

    const int B = in_sizes[4];            // 256
    const int S = in_sizes[5] / B;        // 512
    (void)n_in; (void)out_size;

    int E0 = S / 4;                       // 128
    int E1 = S / 2;                       // 256
    int E2 = (3 * S) / 4;                 // 384

    size_t smem = 2048                    // 4 groups x 2 phases x 256B
                + (size_t)S * 4           // shared mask
                + 128;                    // reduction scratch

    k_crf_forward<<<B, 256, smem>>>(feats, startT, endT, trans,
                                    mask, labels, S, E0, E1, E2);
    k_finalize<<<1, 256>>>((float*)d_out, conf, B);
}